// round 5
// baseline (speedup 1.0000x reference)
#include <cuda_runtime.h>

// Fixed problem shape
#define HH   50
#define GG   200
#define TT   2048
#define BB   8192
#define BPB  64          // batches per block
#define NW   20          // warps per block
#define NTHR 640

typedef unsigned long long ull;

// ---- packed f32x2 helpers (PTX-only; ptxas never auto-fuses) ----
__device__ __forceinline__ ull pack2(float lo, float hi) {
    ull r; asm("mov.b64 %0, {%1, %2};" : "=l"(r) : "f"(lo), "f"(hi)); return r;
}
__device__ __forceinline__ void unpack2(ull v, float &lo, float &hi) {
    asm("mov.b64 {%0, %1}, %2;" : "=f"(lo), "=f"(hi) : "l"(v));
}
__device__ __forceinline__ ull ffma2(ull a, ull b, ull c) {
    ull d; asm("fma.rn.f32x2 %0, %1, %2, %3;" : "=l"(d) : "l"(a), "l"(b), "l"(c)); return d;
}
__device__ __forceinline__ ull fadd2(ull a, ull b) {
    ull d; asm("add.rn.f32x2 %0, %1, %2;" : "=l"(d) : "l"(a), "l"(b)); return d;
}

// accurate activations (EX2 + RCP ~1e-7), overflow-safe
__device__ __forceinline__ float sigm(float x) {
    return __fdividef(1.0f, 1.0f + __expf(-x));
}
__device__ __forceinline__ float tanh_r(float x) {
    float a = fabsf(x);
    float e = __expf(2.0f * a);
    float r = 1.0f - __fdividef(2.0f, e + 1.0f);
    return copysignf(r, x);
}

// ---- shared layout ----
// wsh  : float[200][52]   41600 B @ 0        (W_hh rows, j-padded)
// hsw  : 64 x 256 B       16384 B @ 41600    (h, XOR-swizzled 16B units)
// zsh  : ull[200][32]     51200 B @ 57984    (z pre-activations, [gate][lane])
// xt   : float[64][66]    16896 B @ 109184   (x tile)
// wbsh : float2[200]       1600 B @ 126080   (W_ih[g], b_ih+b_hh)
// wlin : float[52]          208 B @ 127680
#define OFF_W    0
#define OFF_H    41600
#define OFF_Z    57984
#define OFF_X    109184
#define OFF_WB   126080
#define OFF_WLIN 127680
#define SMEM_BYTES 127888
#define XROW 66

__device__ __forceinline__ int h_unit_off(int b, int k) {
    return b * 256 + ((k ^ ((b >> 1) & 7)) << 4);
}
__device__ __forceinline__ int h_elem_off(int b, int j) {
    return b * 256 + (((j >> 2) ^ ((b >> 1) & 7)) << 4) + (j & 3) * 4;
}

__global__ __launch_bounds__(NTHR, 1)
void lstm_persist_kernel(const float* __restrict__ x,
                         const float* __restrict__ W_ih,
                         const float* __restrict__ W_hh,
                         const float* __restrict__ b_ih,
                         const float* __restrict__ b_hh,
                         const float* __restrict__ W_lin,
                         const float* __restrict__ b_lin,
                         float* __restrict__ out)
{
    extern __shared__ char smem[];
    float*  wsh  = (float*)(smem + OFF_W);
    char*   hsw  = smem + OFF_H;
    ull*    zsh  = (ull*)(smem + OFF_Z);
    float*  xt   = (float*)(smem + OFF_X);
    float2* wbsh = (float2*)(smem + OFF_WB);
    float*  wlin = (float*)(smem + OFF_WLIN);

    const int tid = threadIdx.x;
    const int W   = tid >> 5;     // warp id
    const int l   = tid & 31;     // lane = batch pair

    // matvec role: warps 0-9 do gates (i,f) = q 0,1 ; warps 10-19 do (g,o) = q 2,3
    const int qbase = (W < 10) ? 0 : 100;             // row offset of first gate
    const int jb5   = ((W < 10) ? W : W - 10) * 5;    // j-slice [jb5, jb5+5)

    // phase-2 ownership: warps 0-9 own 3 j each (0..29), warps 10-19 own 2 (30..49)
    const int js = (W < 10) ? 3 * W : 2 * W + 10;
    const int jc = (W < 10) ? 3 : 2;

    // ---- init shared ----
    for (int i = tid; i < GG * 52; i += NTHR) {
        int g = i / 52, j = i - g * 52;
        wsh[i] = (j < HH) ? W_hh[g * HH + j] : 0.0f;
    }
    for (int g = tid; g < GG; g += NTHR)
        wbsh[g] = make_float2(W_ih[g], b_ih[g] + b_hh[g]);
    for (int i = tid; i < 52; i += NTHR)
        wlin[i] = (i < HH) ? W_lin[i] : 0.0f;
    for (int i = tid; i < 64 * 64; i += NTHR)
        ((float*)hsw)[i] = 0.0f;

    const int bbase = blockIdx.x * BPB;
    const float* __restrict__ xg = x + (size_t)bbase * TT;

    float cst[3][2];
#pragma unroll
    for (int a = 0; a < 3; ++a) { cst[a][0] = 0.0f; cst[a][1] = 0.0f; }

    const int b0 = 2 * l;
    __syncthreads();

    for (int t = 0; t < TT; ++t) {
        // ---- x tile refill every 64 steps ----
        if ((t & 63) == 0) {
            for (int idx = tid; idx < 64 * 64; idx += NTHR) {
                int ttl = idx & 63, b = idx >> 6;
                xt[ttl * XROW + b] = xg[(size_t)b * TT + t + ttl];
            }
            __syncthreads();
        }

        // ---- phase 1: load h, compute this warp's 10 gate rows ----
        ull h2[2][26];
#pragma unroll
        for (int k = 0; k < 13; ++k) {
            ulonglong2 v0 = *(const ulonglong2*)(hsw + h_unit_off(b0, k));
            ulonglong2 v1 = *(const ulonglong2*)(hsw + h_unit_off(b0 + 1, k));
            h2[0][2 * k] = v0.x;  h2[0][2 * k + 1] = v0.y;
            h2[1][2 * k] = v1.x;  h2[1][2 * k + 1] = v1.y;
        }
        const float2 xv = *(const float2*)&xt[(t & 63) * XROW + b0];

#pragma unroll
        for (int gg = 0; gg < 5; ++gg) {
#pragma unroll
            for (int qq = 0; qq < 2; ++qq) {
                const int g = qbase + qq * 50 + jb5 + gg;
                const float2 wb = wbsh[g];
                ull a00 = pack2(fmaf(wb.x, xv.x, wb.y), 0.0f);
                ull a01 = 0ull;
                ull a10 = pack2(fmaf(wb.x, xv.y, wb.y), 0.0f);
                ull a11 = 0ull;
                const ulonglong2* __restrict__ wr = (const ulonglong2*)(wsh + g * 52);
#pragma unroll
                for (int k = 0; k < 13; ++k) {
                    const ulonglong2 wv = wr[k];         // 4 weights, broadcast LDS.128
                    a00 = ffma2(wv.x, h2[0][2 * k],     a00);
                    a01 = ffma2(wv.y, h2[0][2 * k + 1], a01);
                    a10 = ffma2(wv.x, h2[1][2 * k],     a10);
                    a11 = ffma2(wv.y, h2[1][2 * k + 1], a11);
                }
                const ull s0 = fadd2(a00, a01);
                const ull s1 = fadd2(a10, a11);
                float e0, o0, e1, o1;
                unpack2(s0, e0, o0);
                unpack2(s1, e1, o1);
                zsh[g * 32 + l] = pack2(e0 + o0, e1 + o1);   // (batch0, batch1)
            }
        }
        __syncthreads();

        // ---- phase 2: activations + state update for owned j (all 20 warps) ----
#pragma unroll
        for (int k = 0; k < 3; ++k) {
            if (k < jc) {
                const int j = js + k;
                float zi0, zi1, zf0, zf1, zg0, zg1, zo0, zo1;
                unpack2(zsh[(      j) * 32 + l], zi0, zi1);
                unpack2(zsh[( 50 + j) * 32 + l], zf0, zf1);
                unpack2(zsh[(100 + j) * 32 + l], zg0, zg1);
                unpack2(zsh[(150 + j) * 32 + l], zo0, zo1);

                {
                    const float iv = sigm(zi0), fv = sigm(zf0);
                    const float gv = tanh_r(zg0), ov = sigm(zo0);
                    const float c  = fmaf(fv, cst[k][0], iv * gv);
                    cst[k][0] = c;
                    *(float*)(hsw + h_elem_off(b0, j)) = ov * tanh_r(c);
                }
                {
                    const float iv = sigm(zi1), fv = sigm(zf1);
                    const float gv = tanh_r(zg1), ov = sigm(zo1);
                    const float c  = fmaf(fv, cst[k][1], iv * gv);
                    cst[k][1] = c;
                    *(float*)(hsw + h_elem_off(b0 + 1, j)) = ov * tanh_r(c);
                }
            }
        }
        __syncthreads();
    }

    // ---- final projection (warp 0: lane l -> batches b0, b0+1) ----
    if (W == 0) {
        const float bl = b_lin[0];
#pragma unroll
        for (int bb = 0; bb < 2; ++bb) {
            const int b = b0 + bb;
            float s = bl;
            for (int j = 0; j < HH; ++j)
                s = fmaf(wlin[j], *(const float*)(hsw + h_elem_off(b, j)), s);
            out[bbase + b] = s;
        }
    }
}

extern "C" void kernel_launch(void* const* d_in, const int* in_sizes, int n_in,
                              void* d_out, int out_size)
{
    const float* x     = (const float*)d_in[0];
    const float* W_ih  = (const float*)d_in[1];
    const float* W_hh  = (const float*)d_in[2];
    const float* b_ih  = (const float*)d_in[3];
    const float* b_hh  = (const float*)d_in[4];
    const float* W_lin = (const float*)d_in[5];
    const float* b_lin = (const float*)d_in[6];
    float* out = (float*)d_out;

    cudaFuncSetAttribute(lstm_persist_kernel,
                         cudaFuncAttributeMaxDynamicSharedMemorySize, SMEM_BYTES);

    lstm_persist_kernel<<<BB / BPB, NTHR, SMEM_BYTES>>>(
        x, W_ih, W_hh, b_ih, b_hh, W_lin, b_lin, out);
}

// round 9
// speedup vs baseline: 2.4645x; 2.4645x over previous
#include <cuda_runtime.h>

// Fixed problem shape
#define HH   50
#define GG   200
#define TT   2048
#define BB   8192
#define BPB  64          // batches per block
#define NW   16          // warps
#define NTHR 512

typedef unsigned long long ull;

// ---- packed f32x2 helpers (PTX-only) ----
__device__ __forceinline__ ull pack2(float lo, float hi) {
    ull r; asm("mov.b64 %0, {%1, %2};" : "=l"(r) : "f"(lo), "f"(hi)); return r;
}
__device__ __forceinline__ void unpack2(ull v, float &lo, float &hi) {
    asm("mov.b64 {%0, %1}, %2;" : "=f"(lo), "=f"(hi) : "l"(v));
}
__device__ __forceinline__ ull ffma2(ull a, ull b, ull c) {
    ull d; asm("fma.rn.f32x2 %0, %1, %2, %3;" : "=l"(d) : "l"(a), "l"(b), "l"(c)); return d;
}
__device__ __forceinline__ ull fadd2(ull a, ull b) {
    ull d; asm("add.rn.f32x2 %0, %1, %2;" : "=l"(d) : "l"(a), "l"(b)); return d;
}

// accurate activations (EX2 + RCP ~1e-7), overflow-safe
__device__ __forceinline__ float sigm(float x) {
    return __fdividef(1.0f, 1.0f + __expf(-x));
}
__device__ __forceinline__ float tanh_r(float x) {
    float a = fabsf(x);
    float e = __expf(2.0f * a);
    float r = 1.0f - __fdividef(2.0f, e + 1.0f);
    return copysignf(r, x);
}

// ---- shared layout ----
// wsh  : float[200][52]   41600 B @ 0        (W_hh rows, j-padded)
// hsw  : 64 x 256 B       16384 B @ 41600    (h, XOR-swizzled 16B units, row=batch)
// zsh  : float[200][64]   51200 B @ 57984    (z, [gate row][batch])
// xt   : float[64][66]    16896 B @ 109184   (x tile)
// wbsh : float2[200]       1600 B @ 126080   (W_ih[g], b_ih+b_hh)
// wlin : float[52]          208 B @ 127680
#define OFF_W    0
#define OFF_H    41600
#define OFF_Z    57984
#define OFF_X    109184
#define OFF_WB   126080
#define OFF_WLIN 127680
#define SMEM_BYTES 127888
#define XROW 66

// 16B unit k of batch-row b (h holds j-pairs: unit k covers j in [4k,4k+4))
__device__ __forceinline__ int h_unit_off(int b, int k) {
    return b * 256 + ((k ^ (b & 7)) << 4);
}
__device__ __forceinline__ int h_elem_off(int b, int j) {
    return b * 256 + (((j >> 2) ^ (b & 7)) << 4) + (j & 3) * 4;
}

// per-group barrier (group 0 -> id 1, group 1 -> id 2), 256 threads each
#define GBAR(g) asm volatile("bar.sync %0, 256;" :: "r"((g) + 1) : "memory")

__global__ __launch_bounds__(NTHR, 1)
void lstm_persist_kernel(const float* __restrict__ x,
                         const float* __restrict__ W_ih,
                         const float* __restrict__ W_hh,
                         const float* __restrict__ b_ih,
                         const float* __restrict__ b_hh,
                         const float* __restrict__ W_lin,
                         const float* __restrict__ b_lin,
                         float* __restrict__ out)
{
    extern __shared__ char smem[];
    float*  wsh  = (float*)(smem + OFF_W);
    char*   hsw  = smem + OFF_H;
    float*  zsh  = (float*)(smem + OFF_Z);
    float*  xt   = (float*)(smem + OFF_X);
    float2* wbsh = (float2*)(smem + OFF_WB);
    float*  wlin = (float*)(smem + OFF_WLIN);

    const int tid   = threadIdx.x;
    const int W     = tid >> 5;
    const int l     = tid & 31;
    const int group = W >> 3;        // batch group: 0 -> batches 0-31, 1 -> 32-63
    const int w8    = W & 7;         // warp within group
    const int b     = group * 32 + l;  // this lane's batch (within block)

    // matvec: rows [w8*25, w8*25+25) for this group's batches
    const int r0 = w8 * 25;
    // phase 2: j ownership within group (6,6,6,6,6,6,7,7)
    const int js = (w8 < 6) ? 6 * w8 : 36 + 7 * (w8 - 6);
    const int jc = (w8 < 6) ? 6 : 7;

    // ---- init shared ----
    for (int i = tid; i < GG * 52; i += NTHR) {
        int g = i / 52, j = i - g * 52;
        wsh[i] = (j < HH) ? W_hh[g * HH + j] : 0.0f;
    }
    for (int g = tid; g < GG; g += NTHR)
        wbsh[g] = make_float2(W_ih[g], b_ih[g] + b_hh[g]);
    for (int i = tid; i < 52; i += NTHR)
        wlin[i] = (i < HH) ? W_lin[i] : 0.0f;
    for (int i = tid; i < 64 * 64; i += NTHR)
        ((float*)hsw)[i] = 0.0f;

    const int bbase = blockIdx.x * BPB;
    const float* __restrict__ xg = x + (size_t)bbase * TT;

    float cst[7];
#pragma unroll
    for (int a = 0; a < 7; ++a) cst[a] = 0.0f;

    __syncthreads();

    for (int t = 0; t < TT; ++t) {
        // ---- x tile refill every 64 steps (full-block sync) ----
        if ((t & 63) == 0) {
            __syncthreads();
            for (int idx = tid; idx < 64 * 64; idx += NTHR) {
                int tl = idx & 63, bb = idx >> 6;
                xt[tl * XROW + bb] = xg[(size_t)bb * TT + t + tl];
            }
            __syncthreads();
        }

        // ---- matvec: this lane's batch, 25 gate rows ----
        ull h2[26];
#pragma unroll
        for (int k = 0; k < 13; ++k) {
            ulonglong2 v = *(const ulonglong2*)(hsw + h_unit_off(b, k));
            h2[2 * k]     = v.x;
            h2[2 * k + 1] = v.y;
        }
        const float xv = xt[(t & 63) * XROW + b];

#pragma unroll 5
        for (int rr = 0; rr < 25; ++rr) {
            const int g = r0 + rr;
            const float2 wb = wbsh[g];
            ull a0 = pack2(fmaf(wb.x, xv, wb.y), 0.0f);
            ull a1 = 0ull, a2 = 0ull, a3 = 0ull;
            const ulonglong2* __restrict__ wr = (const ulonglong2*)(wsh + g * 52);
#pragma unroll
            for (int k = 0; k < 13; ++k) {
                const ulonglong2 wv = wr[k];      // 4 weights, broadcast LDS.128
                if (k & 1) {
                    a2 = ffma2(wv.x, h2[2 * k],     a2);
                    a3 = ffma2(wv.y, h2[2 * k + 1], a3);
                } else {
                    a0 = ffma2(wv.x, h2[2 * k],     a0);
                    a1 = ffma2(wv.y, h2[2 * k + 1], a1);
                }
            }
            const ull s = fadd2(fadd2(a0, a2), fadd2(a1, a3));
            float e, o;
            unpack2(s, e, o);
            zsh[g * 64 + b] = e + o;
        }
        GBAR(group);

        // ---- phase 2: activations + state update for owned j ----
#pragma unroll
        for (int kk = 0; kk < 7; ++kk) {
            if (kk < jc) {
                const int j = js + kk;
                const float zi = zsh[(      j) * 64 + b];
                const float zf = zsh[( 50 + j) * 64 + b];
                const float zg = zsh[(100 + j) * 64 + b];
                const float zo = zsh[(150 + j) * 64 + b];

                const float iv = sigm(zi);
                const float fv = sigm(zf);
                const float gv = tanh_r(zg);
                const float ov = sigm(zo);
                const float c  = fmaf(fv, cst[kk], iv * gv);
                cst[kk] = c;
                *(float*)(hsw + h_elem_off(b, j)) = ov * tanh_r(c);
            }
        }
        GBAR(group);
    }

    // ---- final projection (warp 0 of each group; lane = batch) ----
    if (w8 == 0) {
        const float bl = b_lin[0];
        float s = bl;
#pragma unroll
        for (int j = 0; j < HH; ++j)
            s = fmaf(wlin[j], *(const float*)(hsw + h_elem_off(b, j)), s);
        out[bbase + b] = s;
    }
}

extern "C" void kernel_launch(void* const* d_in, const int* in_sizes, int n_in,
                              void* d_out, int out_size)
{
    const float* x     = (const float*)d_in[0];
    const float* W_ih  = (const float*)d_in[1];
    const float* W_hh  = (const float*)d_in[2];
    const float* b_ih  = (const float*)d_in[3];
    const float* b_hh  = (const float*)d_in[4];
    const float* W_lin = (const float*)d_in[5];
    const float* b_lin = (const float*)d_in[6];
    float* out = (float*)d_out;

    cudaFuncSetAttribute(lstm_persist_kernel,
                         cudaFuncAttributeMaxDynamicSharedMemorySize, SMEM_BYTES);

    lstm_persist_kernel<<<BB / BPB, NTHR, SMEM_BYTES>>>(
        x, W_ih, W_hh, b_ih, b_hh, W_lin, b_lin, out);
}

// round 10
// speedup vs baseline: 2.4784x; 1.0056x over previous
#include <cuda_runtime.h>

// Fixed problem shape
#define HH   50
#define GG   200
#define TT   2048
#define BB   8192
#define BPB  64          // batches per block
#define NW   16
#define NTHR 512

typedef unsigned long long ull;

// ---- packed f32x2 helpers (PTX-only) ----
__device__ __forceinline__ ull pack2(float lo, float hi) {
    ull r; asm("mov.b64 %0, {%1, %2};" : "=l"(r) : "f"(lo), "f"(hi)); return r;
}
__device__ __forceinline__ void unpack2(ull v, float &lo, float &hi) {
    asm("mov.b64 {%0, %1}, %2;" : "=f"(lo), "=f"(hi) : "l"(v));
}
__device__ __forceinline__ ull ffma2(ull a, ull b, ull c) {
    ull d; asm("fma.rn.f32x2 %0, %1, %2, %3;" : "=l"(d) : "l"(a), "l"(b), "l"(c)); return d;
}
__device__ __forceinline__ ull fadd2(ull a, ull b) {
    ull d; asm("add.rn.f32x2 %0, %1, %2;" : "=l"(d) : "l"(a), "l"(b)); return d;
}

// ---- MUFU.TANH activations ----
__device__ __forceinline__ float tanha(float x) {
    float r; asm("tanh.approx.f32 %0, %1;" : "=f"(r) : "f"(x)); return r;
}
__device__ __forceinline__ float sigm(float x) {       // 0.5*tanh(x/2)+0.5
    return fmaf(0.5f, tanha(0.5f * x), 0.5f);
}

// ---- shared layout ----
// wsh  : float[200][52]   41600 B @ 0        (W_hh rows, j-padded)
// hsw  : 64 x 256 B       16384 B @ 41600    (h, XOR-swizzled 16B units, row=batch)
// zA   : ull[200][32]     51200 B @ 57984    (partial z, j 0..27,  [row][pair])
// zB   : ull[200][32]     51200 B @ 109184   (partial z, j 28..51)
// xt   : float[64][66]    16896 B @ 160384
// wbsh : float2[200]       1600 B @ 177280   (W_ih[g], b_ih+b_hh)
// wlin : float[52]          208 B @ 178880
#define OFF_W    0
#define OFF_H    41600
#define OFF_ZA   57984
#define OFF_ZB   109184
#define OFF_X    160384
#define OFF_WB   177280
#define OFF_WLIN 178880
#define SMEM_BYTES 179088
#define XROW 66

// 16B unit k of batch-row b (pair-swizzled like R4: conflict-free for lane=pair)
__device__ __forceinline__ int h_unit_off(int b, int k) {
    return b * 256 + ((k ^ ((b >> 1) & 7)) << 4);
}
__device__ __forceinline__ int h_elem_off(int b, int j) {
    return b * 256 + (((j >> 2) ^ ((b >> 1) & 7)) << 4) + (j & 3) * 4;
}

__global__ __launch_bounds__(NTHR, 1)
void lstm_persist_kernel(const float* __restrict__ x,
                         const float* __restrict__ W_ih,
                         const float* __restrict__ W_hh,
                         const float* __restrict__ b_ih,
                         const float* __restrict__ b_hh,
                         const float* __restrict__ W_lin,
                         const float* __restrict__ b_lin,
                         float* __restrict__ out)
{
    extern __shared__ char smem[];
    float*  wsh  = (float*)(smem + OFF_W);
    char*   hsw  = smem + OFF_H;
    ull*    zA   = (ull*)(smem + OFF_ZA);
    ull*    zB   = (ull*)(smem + OFF_ZB);
    float*  xt   = (float*)(smem + OFF_X);
    float2* wbsh = (float2*)(smem + OFF_WB);
    float*  wlin = (float*)(smem + OFF_WLIN);

    const int tid  = threadIdx.x;
    const int W    = tid >> 5;
    const int l    = tid & 31;      // lane = batch pair (batches 2l, 2l+1)
    const int p    = W >> 1;        // warp pair: rows [25p, 25p+25)
    const int half = W & 1;         // 0 = j 0..27 (7 units), 1 = j 28..51 (6 units)

    const int r0    = p * 25;
    const int kbase = half ? 7 : 0;
    const int KU    = half ? 6 : 7;
    ull* zout = half ? zB : zA;

    // phase-2 j ownership: warps 0..13 own 3 j, warps 14..15 own 4 j (total 50)
    const int js = (W < 14) ? 3 * W : 42 + 4 * (W - 14);
    const int jc = (W < 14) ? 3 : 4;

    // ---- init shared ----
    for (int i = tid; i < GG * 52; i += NTHR) {
        int g = i / 52, j = i - g * 52;
        wsh[i] = (j < HH) ? W_hh[g * HH + j] : 0.0f;
    }
    for (int g = tid; g < GG; g += NTHR)
        wbsh[g] = make_float2(W_ih[g], b_ih[g] + b_hh[g]);
    for (int i = tid; i < 52; i += NTHR)
        wlin[i] = (i < HH) ? W_lin[i] : 0.0f;
    for (int i = tid; i < 64 * 64; i += NTHR)
        ((float*)hsw)[i] = 0.0f;

    const int bbase = blockIdx.x * BPB;
    const float* __restrict__ xg = x + (size_t)bbase * TT;
    const int b0 = 2 * l;

    float cst[4][2];
#pragma unroll
    for (int a = 0; a < 4; ++a) { cst[a][0] = 0.0f; cst[a][1] = 0.0f; }

    __syncthreads();

    for (int t = 0; t < TT; ++t) {
        // ---- x tile refill every 64 steps ----
        if ((t & 63) == 0) {
            for (int idx = tid; idx < 64 * 64; idx += NTHR) {
                int tl = idx & 63, bb = idx >> 6;
                xt[tl * XROW + bb] = xg[(size_t)bb * TT + t + tl];
            }
            __syncthreads();
        }

        // ---- load this warp's h j-half, both batches of the pair ----
        ull h2[2][14];
#pragma unroll
        for (int k = 0; k < 7; ++k) {
            if (k < KU) {
                ulonglong2 v0 = *(const ulonglong2*)(hsw + h_unit_off(b0,     kbase + k));
                ulonglong2 v1 = *(const ulonglong2*)(hsw + h_unit_off(b0 + 1, kbase + k));
                h2[0][2 * k] = v0.x;  h2[0][2 * k + 1] = v0.y;
                h2[1][2 * k] = v1.x;  h2[1][2 * k + 1] = v1.y;
            }
        }
        const float2 xv = *(const float2*)&xt[(t & 63) * XROW + b0];

        // ---- matvec: 25 rows, this j-half ----
#pragma unroll 5
        for (int rr = 0; rr < 25; ++rr) {
            const int g = r0 + rr;
            ull a00, a01, a10, a11;
            if (half == 0) {                 // A carries bias + x contribution
                const float2 wb = wbsh[g];
                a00 = pack2(fmaf(wb.x, xv.x, wb.y), 0.0f);
                a10 = pack2(fmaf(wb.x, xv.y, wb.y), 0.0f);
            } else {
                a00 = 0ull; a10 = 0ull;
            }
            a01 = 0ull; a11 = 0ull;
            const ulonglong2* __restrict__ wr = (const ulonglong2*)(wsh + g * 52);
#pragma unroll
            for (int k = 0; k < 7; ++k) {
                if (k < KU) {
                    const ulonglong2 wv = wr[kbase + k];   // 4 weights, broadcast LDS.128
                    a00 = ffma2(wv.x, h2[0][2 * k],     a00);
                    a01 = ffma2(wv.y, h2[0][2 * k + 1], a01);
                    a10 = ffma2(wv.x, h2[1][2 * k],     a10);
                    a11 = ffma2(wv.y, h2[1][2 * k + 1], a11);
                }
            }
            const ull s0 = fadd2(a00, a01);
            const ull s1 = fadd2(a10, a11);
            float e0, o0, e1, o1;
            unpack2(s0, e0, o0);
            unpack2(s1, e1, o1);
            zout[g * 32 + l] = pack2(e0 + o0, e1 + o1);    // (batch0, batch1) partial
        }
        __syncthreads();

        // ---- phase 2: combine halves, activations, state update ----
#pragma unroll
        for (int kk = 0; kk < 4; ++kk) {
            if (kk < jc) {
                const int j = js + kk;
                const ull zi2 = fadd2(zA[(      j) * 32 + l], zB[(      j) * 32 + l]);
                const ull zf2 = fadd2(zA[( 50 + j) * 32 + l], zB[( 50 + j) * 32 + l]);
                const ull zg2 = fadd2(zA[(100 + j) * 32 + l], zB[(100 + j) * 32 + l]);
                const ull zo2 = fadd2(zA[(150 + j) * 32 + l], zB[(150 + j) * 32 + l]);
                float zi0, zi1, zf0, zf1, zg0, zg1, zo0, zo1;
                unpack2(zi2, zi0, zi1);
                unpack2(zf2, zf0, zf1);
                unpack2(zg2, zg0, zg1);
                unpack2(zo2, zo0, zo1);
                {
                    const float iv = sigm(zi0), fv = sigm(zf0);
                    const float gv = tanha(zg0), ov = sigm(zo0);
                    const float c  = fmaf(fv, cst[kk][0], iv * gv);
                    cst[kk][0] = c;
                    *(float*)(hsw + h_elem_off(b0, j)) = ov * tanha(c);
                }
                {
                    const float iv = sigm(zi1), fv = sigm(zf1);
                    const float gv = tanha(zg1), ov = sigm(zo1);
                    const float c  = fmaf(fv, cst[kk][1], iv * gv);
                    cst[kk][1] = c;
                    *(float*)(hsw + h_elem_off(b0 + 1, j)) = ov * tanha(c);
                }
            }
        }
        __syncthreads();
    }

    // ---- final projection (warp 0; lane = pair -> batches 2l, 2l+1) ----
    if (W == 0) {
        const float bl = b_lin[0];
#pragma unroll
        for (int bb = 0; bb < 2; ++bb) {
            const int b = b0 + bb;
            float s = bl;
            for (int j = 0; j < HH; ++j)
                s = fmaf(wlin[j], *(const float*)(hsw + h_elem_off(b, j)), s);
            out[bbase + b] = s;
        }
    }
}

extern "C" void kernel_launch(void* const* d_in, const int* in_sizes, int n_in,
                              void* d_out, int out_size)
{
    const float* x     = (const float*)d_in[0];
    const float* W_ih  = (const float*)d_in[1];
    const float* W_hh  = (const float*)d_in[2];
    const float* b_ih  = (const float*)d_in[3];
    const float* b_hh  = (const float*)d_in[4];
    const float* W_lin = (const float*)d_in[5];
    const float* b_lin = (const float*)d_in[6];
    float* out = (float*)d_out;

    cudaFuncSetAttribute(lstm_persist_kernel,
                         cudaFuncAttributeMaxDynamicSharedMemorySize, SMEM_BYTES);

    lstm_persist_kernel<<<BB / BPB, NTHR, SMEM_BYTES>>>(
        x, W_ih, W_hh, b_ih, b_hh, W_lin, b_lin, out);
}

// round 11
// speedup vs baseline: 3.7119x; 1.4977x over previous
#include <cuda_runtime.h>

// Fixed problem shape
#define HH   50
#define GG   200
#define TT   2048
#define BB   8192
#define BPB  64          // batches per block
#define NW   8           // warps: each owns 8 batches (4 f32x2 pairs)
#define NTHR 256
#define XROW 66

typedef unsigned long long ull;

// ---- packed f32x2 helpers (PTX-only) ----
__device__ __forceinline__ ull pack2(float lo, float hi) {
    ull r; asm("mov.b64 %0, {%1, %2};" : "=l"(r) : "f"(lo), "f"(hi)); return r;
}
__device__ __forceinline__ void unpack2(ull v, float &lo, float &hi) {
    asm("mov.b64 {%0, %1}, %2;" : "=f"(lo), "=f"(hi) : "l"(v));
}
__device__ __forceinline__ ull ffma2(ull a, ull b, ull c) {
    ull d; asm("fma.rn.f32x2 %0, %1, %2, %3;" : "=l"(d) : "l"(a), "l"(b), "l"(c)); return d;
}

// ---- MUFU.TANH activations (validated: rel_err ~2e-6) ----
__device__ __forceinline__ float tanha(float x) {
    float r; asm("tanh.approx.f32 %0, %1;" : "=f"(r) : "f"(x)); return r;
}
__device__ __forceinline__ float sigm(float x) {       // 0.5*tanh(x/2)+0.5
    return fmaf(0.5f, tanha(0.5f * x), 0.5f);
}

// ---- shared layout (bytes) ----
// wsh  : float[224][53]   47488 @ 0       W_hh rows padded (rows>=200 zero; 53 kills bank conflicts)
// wbsh : float2[224]       1792 @ 47488   (W_ih[g], b_ih+b_hh), zero-padded
// wlin : float[52]          208 @ 49280
// xt   : float[64][66]    16896 @ 49504
// hws  : ull[8][4][50]    12800 @ 66400   per-warp h, [pair][j] packed (b0,b1)
// zws  : ull[8][4][224]   57344 @ 79200   per-warp z scratch, [pair][gate]
#define OFF_W    0
#define OFF_WB   47488
#define OFF_WLIN 49280
#define OFF_X    49504
#define OFF_HW   66400
#define OFF_ZW   79200
#define SMEM_BYTES 136544

__global__ __launch_bounds__(NTHR, 1)
void lstm_persist_kernel(const float* __restrict__ x,
                         const float* __restrict__ W_ih,
                         const float* __restrict__ W_hh,
                         const float* __restrict__ b_ih,
                         const float* __restrict__ b_hh,
                         const float* __restrict__ W_lin,
                         const float* __restrict__ b_lin,
                         float* __restrict__ out)
{
    extern __shared__ char smem[];
    float*  wsh  = (float*)(smem + OFF_W);
    float2* wbsh = (float2*)(smem + OFF_WB);
    float*  wlin = (float*)(smem + OFF_WLIN);
    float*  xt   = (float*)(smem + OFF_X);

    const int tid = threadIdx.x;
    const int w   = tid >> 5;
    const int l   = tid & 31;

    ull* __restrict__ hw = (ull*)(smem + OFF_HW) + w * (4 * 50);
    ull* __restrict__ zw = (ull*)(smem + OFF_ZW) + w * (4 * 224);

    // ---- init shared ----
    for (int i = tid; i < 224 * 53; i += NTHR) {
        int g = i / 53, j = i - g * 53;
        wsh[i] = (g < GG && j < HH) ? W_hh[g * HH + j] : 0.0f;
    }
    for (int g = tid; g < 224; g += NTHR)
        wbsh[g] = (g < GG) ? make_float2(W_ih[g], b_ih[g] + b_hh[g])
                           : make_float2(0.0f, 0.0f);
    for (int i = tid; i < 52; i += NTHR)
        wlin[i] = (i < HH) ? W_lin[i] : 0.0f;
    for (int i = tid; i < NW * 4 * 50; i += NTHR)
        ((ull*)(smem + OFF_HW))[i] = 0ull;

    const int bbase = blockIdx.x * BPB;
    const float* __restrict__ xg = x + (size_t)bbase * TT;

    // cell state: [act-slot jj][pair][batch-in-pair]
    float cst[2][4][2];
#pragma unroll
    for (int a = 0; a < 2; ++a)
#pragma unroll
        for (int p = 0; p < 4; ++p) { cst[a][p][0] = 0.0f; cst[a][p][1] = 0.0f; }

    __syncthreads();

    for (int t = 0; t < TT; ++t) {
        // ---- x tile refill every 64 steps (only block-wide sync point) ----
        if ((t & 63) == 0) {
            __syncthreads();
            for (int idx = tid; idx < 64 * 64; idx += NTHR) {
                int tl = idx & 63, bb = idx >> 6;
                xt[tl * XROW + bb] = xg[(size_t)bb * TT + t + tl];
            }
            __syncthreads();
        }
        const int xrow = (t & 63) * XROW;

        // ---- init accumulators: bias + W_ih * x, per pair, packed ----
        ull acc[4][7];
        {
            float2 xp[4];
#pragma unroll
            for (int p = 0; p < 4; ++p)
                xp[p] = *(const float2*)&xt[xrow + w * 8 + 2 * p];
#pragma unroll
            for (int s = 0; s < 7; ++s) {
                const float2 wb = wbsh[l + 32 * s];
#pragma unroll
                for (int p = 0; p < 4; ++p)
                    acc[p][s] = pack2(fmaf(wb.x, xp[p].x, wb.y),
                                      fmaf(wb.x, xp[p].y, wb.y));
            }
        }

        // ---- matvec: z[g] += sum_j W_hh[g][j] * h[j], g = l + 32s ----
#pragma unroll 5
        for (int j = 0; j < HH; ++j) {
            float wv[7];
#pragma unroll
            for (int s = 0; s < 7; ++s)
                wv[s] = wsh[(l + 32 * s) * 53 + j];     // conflict-free scalar LDS
            ull hj[4];
#pragma unroll
            for (int p = 0; p < 4; ++p)
                hj[p] = hw[p * 50 + j];                 // broadcast LDS.64
#pragma unroll
            for (int s = 0; s < 7; ++s) {
                const ull w2 = pack2(wv[s], wv[s]);
#pragma unroll
                for (int p = 0; p < 4; ++p)
                    acc[p][s] = ffma2(w2, hj[p], acc[p][s]);
            }
        }

        // ---- scatter z to per-warp scratch ----
#pragma unroll
        for (int s = 0; s < 7; ++s)
#pragma unroll
            for (int p = 0; p < 4; ++p)
                zw[p * 224 + l + 32 * s] = acc[p][s];
        __syncwarp();

        // ---- activations + state update: lane l owns j = l and j = 32+l ----
#pragma unroll
        for (int jj = 0; jj < 2; ++jj) {
            const int j = jj * 32 + l;
            if (jj == 0 || l < (HH - 32)) {
#pragma unroll
                for (int p = 0; p < 4; ++p) {
                    float zi0, zi1, zf0, zf1, zg0, zg1, zo0, zo1;
                    unpack2(zw[p * 224 +       j], zi0, zi1);
                    unpack2(zw[p * 224 +  50 + j], zf0, zf1);
                    unpack2(zw[p * 224 + 100 + j], zg0, zg1);
                    unpack2(zw[p * 224 + 150 + j], zo0, zo1);
                    float h0, h1;
                    {
                        const float iv = sigm(zi0), fv = sigm(zf0);
                        const float gv = tanha(zg0), ov = sigm(zo0);
                        const float c  = fmaf(fv, cst[jj][p][0], iv * gv);
                        cst[jj][p][0] = c;
                        h0 = ov * tanha(c);
                    }
                    {
                        const float iv = sigm(zi1), fv = sigm(zf1);
                        const float gv = tanha(zg1), ov = sigm(zo1);
                        const float c  = fmaf(fv, cst[jj][p][1], iv * gv);
                        cst[jj][p][1] = c;
                        h1 = ov * tanha(c);
                    }
                    hw[p * 50 + j] = pack2(h0, h1);
                }
            }
        }
        __syncwarp();
    }

    // ---- final projection: lanes 0-7 -> this warp's 8 batches ----
    if (l < 8) {
        const int p  = l >> 1;
        const int hi = l & 1;
        float s = b_lin[0];
#pragma unroll
        for (int j = 0; j < HH; ++j) {
            float h0, h1;
            unpack2(hw[p * 50 + j], h0, h1);
            s = fmaf(wlin[j], hi ? h1 : h0, s);
        }
        out[bbase + w * 8 + l] = s;
    }
}

extern "C" void kernel_launch(void* const* d_in, const int* in_sizes, int n_in,
                              void* d_out, int out_size)
{
    const float* x     = (const float*)d_in[0];
    const float* W_ih  = (const float*)d_in[1];
    const float* W_hh  = (const float*)d_in[2];
    const float* b_ih  = (const float*)d_in[3];
    const float* b_hh  = (const float*)d_in[4];
    const float* W_lin = (const float*)d_in[5];
    const float* b_lin = (const float*)d_in[6];
    float* out = (float*)d_out;

    cudaFuncSetAttribute(lstm_persist_kernel,
                         cudaFuncAttributeMaxDynamicSharedMemorySize, SMEM_BYTES);

    lstm_persist_kernel<<<BB / BPB, NTHR, SMEM_BYTES>>>(
        x, W_ih, W_hh, b_ih, b_hh, W_lin, b_lin, out);
}

// round 12
// speedup vs baseline: 4.0241x; 1.0841x over previous
#include <cuda_runtime.h>

// Fixed problem shape
#define HH   50
#define GG   200
#define TT   2048
#define BB   8192
#define BPB  64          // batches per block
#define NW   8           // warps: each owns 8 batches (4 f32x2 pairs)
#define NTHR 256
#define XROW 66

typedef unsigned long long ull;

// ---- packed f32x2 helpers (PTX-only) ----
__device__ __forceinline__ ull pack2(float lo, float hi) {
    ull r; asm("mov.b64 %0, {%1, %2};" : "=l"(r) : "f"(lo), "f"(hi)); return r;
}
__device__ __forceinline__ void unpack2(ull v, float &lo, float &hi) {
    asm("mov.b64 {%0, %1}, %2;" : "=f"(lo), "=f"(hi) : "l"(v));
}
__device__ __forceinline__ ull ffma2(ull a, ull b, ull c) {
    ull d; asm("fma.rn.f32x2 %0, %1, %2, %3;" : "=l"(d) : "l"(a), "l"(b), "l"(c)); return d;
}

// ---- MUFU.TANH activations (validated: rel_err ~2e-6) ----
__device__ __forceinline__ float tanha(float x) {
    float r; asm("tanh.approx.f32 %0, %1;" : "=f"(r) : "f"(x)); return r;
}
__device__ __forceinline__ float sigm(float x) {       // 0.5*tanh(x/2)+0.5
    return fmaf(0.5f, tanha(0.5f * x), 0.5f);
}

// ---- shared layout (bytes) ----
// wsh  : float[224][53]   47488 @ 0       W_hh rows padded (rows>=200 zero; 53 kills bank conflicts)
// wbsh : float2[224]       1792 @ 47488   (W_ih[g], b_ih+b_hh), zero-padded
// wlin : float[52]          208 @ 49280
// xt   : float[64][66]    16896 @ 49504
// hws  : ull[8][4][50]    12800 @ 66400   per-warp h, [pair][j] packed (b0,b1)
// zws  : ull[8][4][224]   57344 @ 79200   per-warp z scratch, [pair][gate]
#define OFF_W    0
#define OFF_WB   47488
#define OFF_WLIN 49280
#define OFF_X    49504
#define OFF_HW   66400
#define OFF_ZW   79200
#define SMEM_BYTES 136544

__global__ __launch_bounds__(NTHR, 1)
void lstm_persist_kernel(const float* __restrict__ x,
                         const float* __restrict__ W_ih,
                         const float* __restrict__ W_hh,
                         const float* __restrict__ b_ih,
                         const float* __restrict__ b_hh,
                         const float* __restrict__ W_lin,
                         const float* __restrict__ b_lin,
                         float* __restrict__ out)
{
    extern __shared__ char smem[];
    float*  wsh  = (float*)(smem + OFF_W);
    float2* wbsh = (float2*)(smem + OFF_WB);
    float*  wlin = (float*)(smem + OFF_WLIN);
    float*  xt   = (float*)(smem + OFF_X);

    const int tid = threadIdx.x;
    const int w   = tid >> 5;
    const int l   = tid & 31;

    ull* __restrict__ hw = (ull*)(smem + OFF_HW) + w * (4 * 50);
    ull* __restrict__ zw = (ull*)(smem + OFF_ZW) + w * (4 * 224);

    // ---- init shared ----
    for (int i = tid; i < 224 * 53; i += NTHR) {
        int g = i / 53, j = i - g * 53;
        wsh[i] = (g < GG && j < HH) ? W_hh[g * HH + j] : 0.0f;
    }
    for (int g = tid; g < 224; g += NTHR)
        wbsh[g] = (g < GG) ? make_float2(W_ih[g], b_ih[g] + b_hh[g])
                           : make_float2(0.0f, 0.0f);
    for (int i = tid; i < 52; i += NTHR)
        wlin[i] = (i < HH) ? W_lin[i] : 0.0f;
    for (int i = tid; i < NW * 4 * 50; i += NTHR)
        ((ull*)(smem + OFF_HW))[i] = 0ull;

    const int bbase = blockIdx.x * BPB;
    const float* __restrict__ xg = x + (size_t)bbase * TT;

    // activation ownership: task a = l + 32k -> (pair = a/50, j = a%50), 200 tasks
    // cell state per task slot k, per batch-in-pair
    float cst[7][2];
#pragma unroll
    for (int k = 0; k < 7; ++k) { cst[k][0] = 0.0f; cst[k][1] = 0.0f; }

    __syncthreads();

    for (int t = 0; t < TT; ++t) {
        // ---- x tile refill every 64 steps (only block-wide sync point) ----
        if ((t & 63) == 0) {
            __syncthreads();
            for (int idx = tid; idx < 64 * 64; idx += NTHR) {
                int tl = idx & 63, bb = idx >> 6;
                xt[tl * XROW + bb] = xg[(size_t)bb * TT + t + tl];
            }
            __syncthreads();
        }
        const int xrow = (t & 63) * XROW;

        // ---- init accumulators: bias + W_ih * x, per pair, packed ----
        ull acc[4][7];
        {
            float2 xp[4];
#pragma unroll
            for (int p = 0; p < 4; ++p)
                xp[p] = *(const float2*)&xt[xrow + w * 8 + 2 * p];
#pragma unroll
            for (int s = 0; s < 7; ++s) {
                const float2 wb = wbsh[l + 32 * s];
#pragma unroll
                for (int p = 0; p < 4; ++p)
                    acc[p][s] = pack2(fmaf(wb.x, xp[p].x, wb.y),
                                      fmaf(wb.x, xp[p].y, wb.y));
            }
        }

        // ---- matvec with explicit one-j-ahead software pipeline ----
        float wvC[7]; ull hjC[4];
#pragma unroll
        for (int s = 0; s < 7; ++s) wvC[s] = wsh[(l + 32 * s) * 53 + 0];
#pragma unroll
        for (int p = 0; p < 4; ++p) hjC[p] = hw[p * 50 + 0];

#pragma unroll 10
        for (int j = 0; j < HH; ++j) {
            // prefetch j+1 (last iter harmlessly reloads j=0)
            const int jn = (j + 1 < HH) ? (j + 1) : 0;
            float wvN[7]; ull hjN[4];
#pragma unroll
            for (int s = 0; s < 7; ++s) wvN[s] = wsh[(l + 32 * s) * 53 + jn];
#pragma unroll
            for (int p = 0; p < 4; ++p) hjN[p] = hw[p * 50 + jn];

            // consume current j
#pragma unroll
            for (int s = 0; s < 7; ++s) {
                const ull w2 = pack2(wvC[s], wvC[s]);
#pragma unroll
                for (int p = 0; p < 4; ++p)
                    acc[p][s] = ffma2(w2, hjC[p], acc[p][s]);
            }
            // rotate
#pragma unroll
            for (int s = 0; s < 7; ++s) wvC[s] = wvN[s];
#pragma unroll
            for (int p = 0; p < 4; ++p) hjC[p] = hjN[p];
        }

        // ---- scatter z to per-warp scratch ----
#pragma unroll
        for (int s = 0; s < 7; ++s)
#pragma unroll
            for (int p = 0; p < 4; ++p)
                zw[p * 224 + l + 32 * s] = acc[p][s];
        __syncwarp();

        // ---- activations: balanced tasks a = l + 32k over (pair, j) ----
#pragma unroll
        for (int k = 0; k < 7; ++k) {
            const int a = l + 32 * k;
            if (k < 6 || a < 200) {
                const int p = a / 50;
                const int j = a - 50 * p;
                float zi0, zi1, zf0, zf1, zg0, zg1, zo0, zo1;
                unpack2(zw[p * 224 +       j], zi0, zi1);
                unpack2(zw[p * 224 +  50 + j], zf0, zf1);
                unpack2(zw[p * 224 + 100 + j], zg0, zg1);
                unpack2(zw[p * 224 + 150 + j], zo0, zo1);
                float h0, h1;
                {
                    const float iv = sigm(zi0), fv = sigm(zf0);
                    const float gv = tanha(zg0), ov = sigm(zo0);
                    const float c  = fmaf(fv, cst[k][0], iv * gv);
                    cst[k][0] = c;
                    h0 = ov * tanha(c);
                }
                {
                    const float iv = sigm(zi1), fv = sigm(zf1);
                    const float gv = tanha(zg1), ov = sigm(zo1);
                    const float c  = fmaf(fv, cst[k][1], iv * gv);
                    cst[k][1] = c;
                    h1 = ov * tanha(c);
                }
                hw[p * 50 + j] = pack2(h0, h1);
            }
        }
        __syncwarp();
    }

    // ---- final projection: lanes 0-7 -> this warp's 8 batches ----
    if (l < 8) {
        const int p  = l >> 1;
        const int hi = l & 1;
        float s = b_lin[0];
#pragma unroll
        for (int j = 0; j < HH; ++j) {
            float h0, h1;
            unpack2(hw[p * 50 + j], h0, h1);
            s = fmaf(wlin[j], hi ? h1 : h0, s);
        }
        out[bbase + w * 8 + l] = s;
    }
}

extern "C" void kernel_launch(void* const* d_in, const int* in_sizes, int n_in,
                              void* d_out, int out_size)
{
    const float* x     = (const float*)d_in[0];
    const float* W_ih  = (const float*)d_in[1];
    const float* W_hh  = (const float*)d_in[2];
    const float* b_ih  = (const float*)d_in[3];
    const float* b_hh  = (const float*)d_in[4];
    const float* W_lin = (const float*)d_in[5];
    const float* b_lin = (const float*)d_in[6];
    float* out = (float*)d_out;

    cudaFuncSetAttribute(lstm_persist_kernel,
                         cudaFuncAttributeMaxDynamicSharedMemorySize, SMEM_BYTES);

    lstm_persist_kernel<<<BB / BPB, NTHR, SMEM_BYTES>>>(
        x, W_ih, W_hh, b_ih, b_hh, W_lin, b_lin, out);
}